// round 1
// baseline (speedup 1.0000x reference)
#include <cuda_runtime.h>

#define FULL 0xffffffffu

static constexpr int B  = 256;
static constexpr int D  = 128;
static constexpr int K  = 8192;
static constexpr int NB = 500000;
static constexpr int NEG_TOT = 2 * B * K;              // 4,194,304
static constexpr long long BANK = (long long)NB * D;   // 64,000,000

__device__ float  g_neg[NEG_TOT];     // [2][B][K] exp-scores, negatives
__device__ float  g_pos[2 * B];       // [2][B]    exp-scores, positives
__device__ double g_sum[2];           // per-view sum of exp-scores
__device__ double g_loss;             // accumulated log terms
__device__ int    g_winner[B];        // last-write-wins scatter resolution

__device__ __forceinline__ float kINV_T()  { return (float)(1.0 / 0.07); }
__device__ __forceinline__ float kMPN()    { return (float)(8192.0 / 500000.0); }
__device__ __forceinline__ float kDENOM()  { return (float)(8192.0 / 500000.0 + 1e-7); }

// --- zero accumulators + compute scatter winners (duplicate idx: last b wins)
__global__ void k_zero(const int* __restrict__ idx) {
    int b = threadIdx.x;
    if (b < 2) g_sum[b] = 0.0;
    if (b == 2) g_loss = 0.0;
    int my = idx[b];
    int win = 1;
    for (int b2 = b + 1; b2 < B; b2++)
        if (idx[b2] == my) win = 0;
    g_winner[b] = win;
}

// --- positives: 512 warps, one (view, b) each
__global__ void k1_pos(const float* __restrict__ f_s, const float* __restrict__ f_t,
                       const float* __restrict__ mv1, const float* __restrict__ mv2,
                       const int* __restrict__ idx) {
    int w    = blockIdx.x * 8 + (threadIdx.x >> 5);   // 0..511
    int lane = threadIdx.x & 31;
    int v = w >> 8;          // 0: out_v1 (mem_v2 x f_s), 1: out_v2 (mem_v1 x f_t)
    int b = w & 255;
    const float4* mem = (const float4*)(v ? mv1 : mv2);
    const float4* f   = (const float4*)(v ? f_t : f_s);
    int row = idx[b];
    float4 fv = f[b * 32 + lane];
    float4 wv = mem[(long long)row * 32 + lane];
    float d = wv.x * fv.x + wv.y * fv.y + wv.z * fv.z + wv.w * fv.w;
    #pragma unroll
    for (int off = 16; off > 0; off >>= 1)
        d += __shfl_xor_sync(FULL, d, off);
    if (lane == 0) {
        float e = expf(d * kINV_T());
        g_pos[w] = e;
        atomicAdd(&g_sum[v], (double)e);
    }
}

// --- negatives: one warp per 8-k chunk. 2 views x 256 b x 1024 chunks.
//     MLP=8 independent LDG.128 gathers per warp; two aligned STG.128 outputs.
__global__ void __launch_bounds__(256) k1_neg(
        const float* __restrict__ f_s, const float* __restrict__ f_t,
        const float* __restrict__ mv1, const float* __restrict__ mv2,
        const int* __restrict__ cidx) {
    int l = blockIdx.x;               // 65536 blocks
    int v = l >> 15;                  // 32768 blocks per view
    int r = l & 32767;
    int w = threadIdx.x >> 5;         // warp in block (8)
    int lane = threadIdx.x & 31;
    int g = r * 8 + w;                // chunk id within view: 0..262143
    int b = g >> 10;                  // 1024 chunks per b
    int c = g & 1023;

    const float4* mem = (const float4*)(v ? mv1 : mv2);
    const float4* f   = (const float4*)(v ? f_t : f_s);
    float4 fv = f[b * 32 + lane];

    int kb = c * 8;
    int rl = (lane < 8) ? cidx[b * K + kb + lane] : 0;

    float4 wv[8];
    #pragma unroll
    for (int j = 0; j < 8; j++) {
        int row = __shfl_sync(FULL, rl, j);
        wv[j] = mem[(long long)row * 32 + lane];
    }
    float d[8];
    #pragma unroll
    for (int j = 0; j < 8; j++)
        d[j] = wv[j].x * fv.x + wv[j].y * fv.y + wv[j].z * fv.z + wv[j].w * fv.w;
    #pragma unroll
    for (int off = 16; off > 0; off >>= 1) {
        #pragma unroll
        for (int j = 0; j < 8; j++)
            d[j] += __shfl_xor_sync(FULL, d[j], off);
    }

    __shared__ float ssum[8];
    if (lane == 0) {
        float e[8];
        #pragma unroll
        for (int j = 0; j < 8; j++) e[j] = expf(d[j] * kINV_T());
        float4* dst = (float4*)(g_neg + ((size_t)(v * B + b) * K + kb));
        dst[0] = make_float4(e[0], e[1], e[2], e[3]);
        dst[1] = make_float4(e[4], e[5], e[6], e[7]);
        ssum[w] = e[0] + e[1] + e[2] + e[3] + e[4] + e[5] + e[6] + e[7];
    }
    __syncthreads();
    if (threadIdx.x == 0) {
        float tot = 0.f;
        #pragma unroll
        for (int j = 0; j < 8; j++) tot += ssum[j];
        atomicAdd(&g_sum[v], (double)tot);
    }
}

// --- loss reduction: Z from g_sum, then log terms over all scores
__global__ void k2_loss() {
    double Z0 = g_sum[0] * (500000.0 / 2097408.0);   // mean * n_data
    double Z1 = g_sum[1] * (500000.0 / 2097408.0);
    float Zf0 = (float)Z0, Zf1 = (float)Z1;

    int total  = NEG_TOT + 2 * B;
    int stride = gridDim.x * blockDim.x;
    double acc = 0.0;
    for (int i = blockIdx.x * blockDim.x + threadIdx.x; i < total; i += stride) {
        float t;
        if (i < 2 * B) {
            float Zf = (i < B) ? Zf0 : Zf1;
            float y = g_pos[i] / Zf;
            t = logf(y / (y + kDENOM()));
        } else {
            int j = i - 2 * B;
            float Zf = (j < B * K) ? Zf0 : Zf1;
            float y = g_neg[j] / Zf;
            t = logf(kMPN() / (y + kDENOM()));
        }
        acc += t;
    }
    #pragma unroll
    for (int off = 16; off > 0; off >>= 1)
        acc += __shfl_xor_sync(FULL, acc, off);
    __shared__ double sh[8];
    int lane = threadIdx.x & 31, wid = threadIdx.x >> 5;
    if (lane == 0) sh[wid] = acc;
    __syncthreads();
    if (threadIdx.x == 0) {
        double s = 0.0;
        for (int j = 0; j < 8; j++) s += sh[j];
        atomicAdd(&g_loss, s);
    }
}

// --- momentum scatter update of the 256 touched rows (into d_out copies)
__global__ void k3_update(const float* __restrict__ f_s, const float* __restrict__ f_t,
                          const float* __restrict__ mv1, const float* __restrict__ mv2,
                          const int* __restrict__ idx, float* __restrict__ out) {
    int u = blockIdx.x;       // 512 blocks
    int v = u >> 8;           // 0: new_v1 = update(mem_v1, f_s), 1: new_v2 = update(mem_v2, f_t)
    int b = u & 255;
    if (!g_winner[b]) return;
    int row = idx[b];
    const float* mem = v ? mv2 : mv1;
    const float* f   = v ? f_t : f_s;
    float* dst = out + 1 + (size_t)v * BANK + (size_t)row * D;
    int t = threadIdx.x;      // 128 threads
    float nv = mem[(long long)row * D + t] * 0.5f + f[b * D + t] * 0.5f;
    float s = nv * nv;
    #pragma unroll
    for (int off = 16; off > 0; off >>= 1)
        s += __shfl_xor_sync(FULL, s, off);
    __shared__ float sh[4];
    if ((t & 31) == 0) sh[t >> 5] = s;
    __syncthreads();
    float tot = sh[0] + sh[1] + sh[2] + sh[3];
    dst[t] = nv / sqrtf(tot);
}

__global__ void k_final(float* __restrict__ out) {
    out[0] = (float)(-g_loss / 256.0);
}

extern "C" void kernel_launch(void* const* d_in, const int* in_sizes, int n_in,
                              void* d_out, int out_size) {
    const float* f_s  = (const float*)d_in[0];
    const float* f_t  = (const float*)d_in[1];
    const float* mv1  = (const float*)d_in[2];
    const float* mv2  = (const float*)d_in[3];
    const int*   idx  = (const int*)d_in[4];
    const int*   cidx = (const int*)d_in[5];
    float* out = (float*)d_out;

    // full-bank copies into output (only 256 rows get overwritten afterwards)
    cudaMemcpyAsync(out + 1,        mv1, sizeof(float) * BANK, cudaMemcpyDeviceToDevice, 0);
    cudaMemcpyAsync(out + 1 + BANK, mv2, sizeof(float) * BANK, cudaMemcpyDeviceToDevice, 0);

    k_zero<<<1, 256>>>(idx);
    k1_pos<<<64, 256>>>(f_s, f_t, mv1, mv2, idx);
    k1_neg<<<65536, 256>>>(f_s, f_t, mv1, mv2, cidx);
    k2_loss<<<1024, 256>>>();
    k3_update<<<512, 128>>>(f_s, f_t, mv1, mv2, idx, out);
    k_final<<<1, 1>>>(out);
}

// round 2
// speedup vs baseline: 1.4353x; 1.4353x over previous
#include <cuda_runtime.h>

#define FULL 0xffffffffu

static constexpr int B  = 256;
static constexpr int D  = 128;
static constexpr int K  = 8192;
static constexpr int NEG_TOT = 2 * B * K;              // 4,194,304
static constexpr long long BANK = 500000LL * D;        // 64,000,000 floats
static constexpr long long BANK4 = BANK / 4;           // 16,000,000 float4
static constexpr long long COPY4 = 2 * (BANK4 - 1);    // shifted float4 stores total

static constexpr int POS_BLOCKS  = 64;
static constexpr int GATHER_BLK  = 65536;              // 8 warps x 8 rows each
static constexpr int COPY_BLK    = 16384;
static constexpr int FUSED_BLOCKS = POS_BLOCKS + GATHER_BLK + COPY_BLK;  // 81984

__device__ float  g_neg[NEG_TOT];     // [2][B][K] exp-scores, negatives
__device__ float  g_pos[2 * B];       // [2][B]    exp-scores, positives
__device__ double g_sum[2];           // per-view sum of exp-scores
__device__ double g_loss;             // accumulated log terms
__device__ int    g_winner[B];        // last-write-wins scatter resolution

__device__ __forceinline__ float kINV_T()  { return (float)(1.0 / 0.07); }
__device__ __forceinline__ float kMPN()    { return (float)(8192.0 / 500000.0); }
__device__ __forceinline__ float kDENOM()  { return (float)(8192.0 / 500000.0 + 1e-7); }

// --- zero accumulators, scatter winners, head/tail copy scalars
__global__ void k_zero(const int* __restrict__ idx,
                       const float* __restrict__ mv1, const float* __restrict__ mv2,
                       float* __restrict__ out) {
    int b = threadIdx.x;
    if (b < 2) g_sum[b] = 0.0;
    if (b == 2) g_loss = 0.0;
    if (b == 3) {
        // elements the shifted float4 copy cannot cover
        out[1] = mv1[0]; out[2] = mv1[1]; out[3] = mv1[2];
        out[BANK] = mv1[BANK - 1];
        out[1 + BANK] = mv2[0]; out[2 + BANK] = mv2[1]; out[3 + BANK] = mv2[2];
        out[2 * BANK] = mv2[BANK - 1];
    }
    int my = idx[b];
    int win = 1;
    for (int b2 = b + 1; b2 < B; b2++)
        if (idx[b2] == my) win = 0;
    g_winner[b] = win;
}

// --- fused: positives + negative gather + bank copy, interleaved block roles
__global__ void __launch_bounds__(256) k_fused(
        const float* __restrict__ f_s, const float* __restrict__ f_t,
        const float* __restrict__ mv1, const float* __restrict__ mv2,
        const int* __restrict__ idx, const int* __restrict__ cidx,
        float* __restrict__ out) {
    int bid = blockIdx.x;
    int lane = threadIdx.x & 31;
    int wrp  = threadIdx.x >> 5;

    if (bid < POS_BLOCKS) {
        // ---- positives: 512 warps, one (view, b) each
        int w = bid * 8 + wrp;
        int v = w >> 8;
        int b = w & 255;
        const float4* mem = (const float4*)(v ? mv1 : mv2);
        const float4* f   = (const float4*)(v ? f_t : f_s);
        int row = idx[b];
        float4 fv = f[b * 32 + lane];
        float4 wv = mem[(long long)row * 32 + lane];
        float d = wv.x * fv.x + wv.y * fv.y + wv.z * fv.z + wv.w * fv.w;
        #pragma unroll
        for (int off = 16; off > 0; off >>= 1)
            d += __shfl_xor_sync(FULL, d, off);
        if (lane == 0) {
            float e = expf(d * kINV_T());
            g_pos[w] = e;
            atomicAdd(&g_sum[v], (double)e);
        }
        return;
    }

    int t = bid - POS_BLOCKS;
    int q = t / 5;
    int r = t - q * 5;

    if (r == 4) {
        // ---- copy block: shifted float4 copy of both banks into out+1
        // out4[v*BANK4 + j] = {bank[4j-1], bank[4j], bank[4j+1], bank[4j+2]}, j in [1, BANK4)
        long long base = (long long)q * 256 + threadIdx.x;
        long long stride = (long long)COPY_BLK * 256;
        float4* out4 = (float4*)out;
        #pragma unroll
        for (int it = 0; it < 8; it++) {
            long long i = base + (long long)it * stride;
            if (i >= COPY4) break;
            int v = (i >= BANK4 - 1);
            long long jp = v ? (i - (BANK4 - 1) + 1) : (i + 1);
            const float* bank = v ? mv2 : mv1;
            float4 c = ((const float4*)bank)[jp];
            float prev = bank[4 * jp - 1];
            float4 o = make_float4(prev, c.x, c.y, c.z);
            __stcs(&out4[(long long)v * BANK4 + jp], o);
        }
        return;
    }

    // ---- gather block: one warp per 8-k chunk
    int g = (t - q) * 8 + wrp;        // gather block id (t - q) in [0, 65536)
    int v = g >> 18;                  // 262144 chunks per view
    int gg = g & 262143;
    int b = gg >> 10;                 // 1024 chunks per b
    int c = gg & 1023;

    const float4* mem = (const float4*)(v ? mv1 : mv2);
    const float4* f   = (const float4*)(v ? f_t : f_s);
    float4 fv = f[b * 32 + lane];

    int kb = c * 8;
    int rl = (lane < 8) ? cidx[b * K + kb + lane] : 0;

    float4 wv[8];
    #pragma unroll
    for (int j = 0; j < 8; j++) {
        int row = __shfl_sync(FULL, rl, j);
        wv[j] = mem[(long long)row * 32 + lane];
    }
    float d[8];
    #pragma unroll
    for (int j = 0; j < 8; j++)
        d[j] = wv[j].x * fv.x + wv[j].y * fv.y + wv[j].z * fv.z + wv[j].w * fv.w;
    #pragma unroll
    for (int off = 16; off > 0; off >>= 1) {
        #pragma unroll
        for (int j = 0; j < 8; j++)
            d[j] += __shfl_xor_sync(FULL, d[j], off);
    }

    __shared__ float ssum[8];
    if (lane == 0) {
        float e[8];
        #pragma unroll
        for (int j = 0; j < 8; j++) e[j] = expf(d[j] * kINV_T());
        float4* dst = (float4*)(g_neg + ((size_t)(v * B + b) * K + kb));
        dst[0] = make_float4(e[0], e[1], e[2], e[3]);
        dst[1] = make_float4(e[4], e[5], e[6], e[7]);
        ssum[wrp] = e[0] + e[1] + e[2] + e[3] + e[4] + e[5] + e[6] + e[7];
    }
    __syncthreads();
    if (threadIdx.x == 0) {
        float tot = 0.f;
        #pragma unroll
        for (int j = 0; j < 8; j++) tot += ssum[j];
        atomicAdd(&g_sum[v], (double)tot);
    }
}

// --- loss reduction: Z from g_sum, then log terms over all scores (MLP=4)
__global__ void __launch_bounds__(256) k2_loss() {
    double Z0 = g_sum[0] * (500000.0 / 2097408.0);   // mean * n_data
    double Z1 = g_sum[1] * (500000.0 / 2097408.0);
    float Zf0 = (float)Z0, Zf1 = (float)Z1;

    const int stride = 512 * 256;                    // 131072 threads
    int tid = blockIdx.x * 256 + threadIdx.x;
    double acc = 0.0;

    // 4,194,304 / 131072 = 32 elems/thread, exactly; 8 groups of 4 independent loads
    #pragma unroll 1
    for (int u = 0; u < 8; u++) {
        int i0 = tid + u * 4 * stride;
        float y0 = g_neg[i0];
        float y1 = g_neg[i0 + stride];
        float y2 = g_neg[i0 + 2 * stride];
        float y3 = g_neg[i0 + 3 * stride];
        // all 4 offsets share the same view (view boundary at multiple of 16*stride)
        float Zf = (i0 < B * K) ? Zf0 : Zf1;
        float t0 = logf(kMPN() / (y0 / Zf + kDENOM()));
        float t1 = logf(kMPN() / (y1 / Zf + kDENOM()));
        float t2 = logf(kMPN() / (y2 / Zf + kDENOM()));
        float t3 = logf(kMPN() / (y3 / Zf + kDENOM()));
        acc += (double)(t0 + t1 + t2 + t3);
    }

    // positives handled by block 0 (256 threads x 2 each)
    if (blockIdx.x == 0) {
        #pragma unroll
        for (int p = 0; p < 2; p++) {
            int i = threadIdx.x + p * 256;
            float Zf = (i < B) ? Zf0 : Zf1;
            float y = g_pos[i] / Zf;
            acc += (double)logf(y / (y + kDENOM()));
        }
    }

    #pragma unroll
    for (int off = 16; off > 0; off >>= 1)
        acc += __shfl_xor_sync(FULL, acc, off);
    __shared__ double sh[8];
    int lane = threadIdx.x & 31, wid = threadIdx.x >> 5;
    if (lane == 0) sh[wid] = acc;
    __syncthreads();
    if (threadIdx.x == 0) {
        double s = 0.0;
        for (int j = 0; j < 8; j++) s += sh[j];
        atomicAdd(&g_loss, s);
    }
}

// --- momentum scatter update of the 256 touched rows (into d_out copies)
__global__ void k3_update(const float* __restrict__ f_s, const float* __restrict__ f_t,
                          const float* __restrict__ mv1, const float* __restrict__ mv2,
                          const int* __restrict__ idx, float* __restrict__ out) {
    int u = blockIdx.x;       // 512 blocks
    int v = u >> 8;           // 0: new_v1 = update(mem_v1, f_s), 1: new_v2 = update(mem_v2, f_t)
    int b = u & 255;
    if (!g_winner[b]) return;
    int row = idx[b];
    const float* mem = v ? mv2 : mv1;
    const float* f   = v ? f_t : f_s;
    float* dst = out + 1 + (size_t)v * BANK + (size_t)row * D;
    int t = threadIdx.x;      // 128 threads
    float nv = mem[(long long)row * D + t] * 0.5f + f[b * D + t] * 0.5f;
    float s = nv * nv;
    #pragma unroll
    for (int off = 16; off > 0; off >>= 1)
        s += __shfl_xor_sync(FULL, s, off);
    __shared__ float sh[4];
    if ((t & 31) == 0) sh[t >> 5] = s;
    __syncthreads();
    float tot = sh[0] + sh[1] + sh[2] + sh[3];
    dst[t] = nv / sqrtf(tot);
}

__global__ void k_final(float* __restrict__ out) {
    out[0] = (float)(-g_loss / 256.0);
}

extern "C" void kernel_launch(void* const* d_in, const int* in_sizes, int n_in,
                              void* d_out, int out_size) {
    const float* f_s  = (const float*)d_in[0];
    const float* f_t  = (const float*)d_in[1];
    const float* mv1  = (const float*)d_in[2];
    const float* mv2  = (const float*)d_in[3];
    const int*   idx  = (const int*)d_in[4];
    const int*   cidx = (const int*)d_in[5];
    float* out = (float*)d_out;

    k_zero<<<1, 256>>>(idx, mv1, mv2, out);
    k_fused<<<FUSED_BLOCKS, 256>>>(f_s, f_t, mv1, mv2, idx, cidx, out);
    k2_loss<<<512, 256>>>();
    k3_update<<<512, 128>>>(f_s, f_t, mv1, mv2, idx, out);
    k_final<<<1, 1>>>(out);
}